// round 15
// baseline (speedup 1.0000x reference)
#include <cuda_runtime.h>
#include <cuda_bf16.h>

// Problem constants (reference shapes are fixed)
#define NN 50000
#define NE 800000
#define IN_CH 64
#define OUT_DIM 128
#define HEADS 4
#define CPH 32           // channels per head
#define NEG 0.2f
#define SCAN_TILE 512

// Scratch (static __device__ — allocations are forbidden)
__device__ float g_xt[NN * OUT_DIM];        // transformed features [N,128] (25.6 MB)
__device__ float g_asrc[NN * HEADS];        // per-node src attention half
__device__ float g_adst[NN * HEADS];        // per-node dst attention half
__device__ float g_linwT[IN_CH * OUT_DIM];  // lin_w transposed [k][t]
__device__ float g_reswT[IN_CH * OUT_DIM];  // res_w transposed [k][t]
__device__ int   g_deg[NN];                 // in-degree per dst (zeroed by k_scan1 each call)
__device__ int   g_rowptr[NN];              // CSR row start
__device__ int   g_cursor[NN];              // fill cursor (== row end after fill)
__device__ int   g_srcs[NE];                // CSR column (source node ids)
__device__ int   g_bsum[128];               // per-block scan totals

__device__ __forceinline__ float lrelu(float v) { return v >= 0.f ? v : NEG * v; }
__device__ __forceinline__ int clampi(int v, int n) {
    return v < 0 ? 0 : (v >= n ? n - 1 : v);
}

// ---------------------------------------------------------------------------
// Kernel 1 (fused): weight transpose (blocks 0..31) + in-degree count (rest)
// g_deg is guaranteed zero at entry: zero-init at load, re-zeroed by k_scan1.
// block = 256
// ---------------------------------------------------------------------------
__global__ void __launch_bounds__(256) k_fused_prep(
    const float* __restrict__ lin_w, const float* __restrict__ res_w,
    const int* __restrict__ ei, int E, int N)
{
    int b = blockIdx.x;
    int t = threadIdx.x;
    if (b < 32) {
        // transpose: 64*128 = 8192 entries over 32 blocks x 256 threads
        int idx = b * 256 + t;
        int k  = idx >> 7;        // 0..63
        int tt = idx & 127;       // 0..127
        g_linwT[k * OUT_DIM + tt] = lin_w[tt * IN_CH + k];
        g_reswT[k * OUT_DIM + tt] = res_w[tt * IN_CH + k];
    } else {
        int e = (b - 32) * 256 + t;
        if (e < E) {
            int d = clampi(ei[E + e], N);
            atomicAdd(&g_deg[d], 1);
        }
    }
}

// ---------------------------------------------------------------------------
// Kernel 2: warp-per-node — xt = x @ lin_w^T (float4), attention halves
// block = 256 (8 warps = 8 nodes), grid = ceil(N/8)
// ---------------------------------------------------------------------------
__global__ void __launch_bounds__(256) k_node_prep(
    const float* __restrict__ x,
    const float* __restrict__ att_src, const float* __restrict__ att_dst, int N)
{
    int w    = threadIdx.x >> 5;
    int lane = threadIdx.x & 31;
    int n = blockIdx.x * 8 + w;
    if (n >= N) return;

    __shared__ float sx[8][IN_CH];
    sx[w][lane]      = x[n * IN_CH + lane];
    sx[w][lane + 32] = x[n * IN_CH + lane + 32];
    __syncwarp();

    float4 acc = make_float4(0.f, 0.f, 0.f, 0.f);
#pragma unroll
    for (int k = 0; k < IN_CH; k++) {
        float xv = sx[w][k];
        float4 wv = *reinterpret_cast<const float4*>(g_linwT + k * OUT_DIM + lane * 4);
        acc.x += xv * wv.x; acc.y += xv * wv.y;
        acc.z += xv * wv.z; acc.w += xv * wv.w;
    }
    *reinterpret_cast<float4*>(g_xt + n * OUT_DIM + lane * 4) = acc;

    // attention halves: lane owns channels [lane*4, lane*4+4) of head hB = lane>>3
    int hB = lane >> 3;
    int cg = (lane & 7) * 4;    // channel offset within head
    float4 s4 = *reinterpret_cast<const float4*>(att_src + hB * CPH + cg);
    float4 d4 = *reinterpret_cast<const float4*>(att_dst + hB * CPH + cg);
    float as = acc.x * s4.x + acc.y * s4.y + acc.z * s4.z + acc.w * s4.w;
    float ad = acc.x * d4.x + acc.y * d4.y + acc.z * d4.z + acc.w * d4.w;
#pragma unroll
    for (int o = 1; o < 8; o <<= 1) {
        as += __shfl_xor_sync(0xFFFFFFFFu, as, o);
        ad += __shfl_xor_sync(0xFFFFFFFFu, ad, o);
    }
    if ((lane & 7) == 0) {
        g_asrc[n * HEADS + hB] = as;
        g_adst[n * HEADS + hB] = ad;
    }
}

// ---------------------------------------------------------------------------
// Kernel 3: per-tile exclusive scan + block totals; zeroes g_deg after read
// grid = ceil(N/512), block = 512
// ---------------------------------------------------------------------------
__global__ void __launch_bounds__(SCAN_TILE) k_scan1(int N)
{
    int t = threadIdx.x;
    int i = blockIdx.x * SCAN_TILE + t;
    int v = 0;
    if (i < N) {
        v = g_deg[i];
        g_deg[i] = 0;    // reset for next call's count phase
    }

    int lane = t & 31, wid = t >> 5;
    int inc = v;
#pragma unroll
    for (int o = 1; o < 32; o <<= 1) {
        int u = __shfl_up_sync(0xFFFFFFFFu, inc, o);
        if (lane >= o) inc += u;
    }
    __shared__ int ws[16];
    if (lane == 31) ws[wid] = inc;
    __syncthreads();
    if (t < 16) {
        int s = ws[t];
        int inc2 = s;
#pragma unroll
        for (int o = 1; o < 16; o <<= 1) {
            int u = __shfl_up_sync(0xFFFFu, inc2, o);
            if (t >= o) inc2 += u;
        }
        ws[t] = inc2 - s;                    // exclusive warp offset
        if (t == 15) g_bsum[blockIdx.x] = inc2;   // block total
    }
    __syncthreads();
    if (i < N) g_rowptr[i] = inc - v + ws[wid];  // block-local exclusive
}

// ---------------------------------------------------------------------------
// Kernel 4 (fused scan2+scan3): each block redundantly scans the <=128 block
// totals (ALL threads hit every __syncthreads — no divergent barriers),
// adds its own exclusive offset, writes rowptr/cursor.
// grid = ceil(N/512), block = 512
// ---------------------------------------------------------------------------
__global__ void __launch_bounds__(SCAN_TILE) k_scan23(int N, int NB)
{
    __shared__ int s[128];
    int t = threadIdx.x;
    if (t < 128) s[t] = (t < NB) ? g_bsum[t] : 0;
    __syncthreads();
    // inclusive Hillis-Steele over s[0..127]; barriers executed by ALL threads
    for (int off = 1; off < 128; off <<= 1) {
        int u = (t < 128 && t >= off) ? s[t - off] : 0;
        __syncthreads();
        if (t < 128) s[t] += u;
        __syncthreads();
    }
    int myoff = (blockIdx.x == 0) ? 0 : s[blockIdx.x - 1];   // exclusive offset
    int i = blockIdx.x * SCAN_TILE + t;
    if (i < N) {
        int r = g_rowptr[i] + myoff;
        g_rowptr[i] = r;
        g_cursor[i] = r;
    }
}

// ---------------------------------------------------------------------------
// Kernel 5: fill CSR columns
// ---------------------------------------------------------------------------
__global__ void __launch_bounds__(256) k_fill(const int* __restrict__ ei, int E, int N)
{
    int e = blockIdx.x * blockDim.x + threadIdx.x;
    if (e >= E) return;
    int s = clampi(ei[e], N);
    int d = clampi(ei[E + e], N);
    int p = atomicAdd(&g_cursor[d], 1);
    g_srcs[p] = s;
}

// ---------------------------------------------------------------------------
// Kernel 6: one warp per dst node — single-pass weighted aggregation,
// unrolled x4 for load MLP; fused self-loop, residual GEMV, LN, LeakyReLU.
// block = 256 (8 warps = 8 nodes), grid = ceil(N/8)
// ---------------------------------------------------------------------------
__global__ void __launch_bounds__(256) k_aggregate(
    const float* __restrict__ x,
    const float* __restrict__ res_b, const float* __restrict__ gat_bias,
    const float* __restrict__ ln_g, const float* __restrict__ ln_b,
    float* __restrict__ out, int N)
{
    int w    = threadIdx.x >> 5;
    int lane = threadIdx.x & 31;
    int d = blockIdx.x * 8 + w;
    if (d >= N) return;

    int r0 = g_rowptr[d];
    int r1 = g_cursor[d];          // == row end after fill

    int hB = lane >> 3;            // head for this lane's 4 channels
    float adst_hB = g_adst[d * HEADS + hB];

    float4 acc0 = make_float4(0.f, 0.f, 0.f, 0.f);
    float4 acc1 = make_float4(0.f, 0.f, 0.f, 0.f);
    float4 acc2 = make_float4(0.f, 0.f, 0.f, 0.f);
    float4 acc3 = make_float4(0.f, 0.f, 0.f, 0.f);
    float exsum = 0.f;

    for (int base = r0; base < r1; base += 32) {
        int cnt = r1 - base; if (cnt > 32) cnt = 32;
        int idx = (base + lane < r1) ? g_srcs[base + lane] : 0;

        int j = 0;
        for (; j + 3 < cnt; j += 4) {
            int s0 = __shfl_sync(0xFFFFFFFFu, idx, j);
            int s1 = __shfl_sync(0xFFFFFFFFu, idx, j + 1);
            int s2 = __shfl_sync(0xFFFFFFFFu, idx, j + 2);
            int s3 = __shfl_sync(0xFFFFFFFFu, idx, j + 3);
            float a0 = g_asrc[s0 * HEADS + hB];
            float a1 = g_asrc[s1 * HEADS + hB];
            float a2 = g_asrc[s2 * HEADS + hB];
            float a3 = g_asrc[s3 * HEADS + hB];
            float4 v0 = *reinterpret_cast<const float4*>(g_xt + s0 * OUT_DIM + lane * 4);
            float4 v1 = *reinterpret_cast<const float4*>(g_xt + s1 * OUT_DIM + lane * 4);
            float4 v2 = *reinterpret_cast<const float4*>(g_xt + s2 * OUT_DIM + lane * 4);
            float4 v3 = *reinterpret_cast<const float4*>(g_xt + s3 * OUT_DIM + lane * 4);
            float ex0 = expf(lrelu(a0 + adst_hB));
            float ex1 = expf(lrelu(a1 + adst_hB));
            float ex2 = expf(lrelu(a2 + adst_hB));
            float ex3 = expf(lrelu(a3 + adst_hB));
            exsum += (ex0 + ex1) + (ex2 + ex3);
            acc0.x += ex0 * v0.x; acc0.y += ex0 * v0.y; acc0.z += ex0 * v0.z; acc0.w += ex0 * v0.w;
            acc1.x += ex1 * v1.x; acc1.y += ex1 * v1.y; acc1.z += ex1 * v1.z; acc1.w += ex1 * v1.w;
            acc2.x += ex2 * v2.x; acc2.y += ex2 * v2.y; acc2.z += ex2 * v2.z; acc2.w += ex2 * v2.w;
            acc3.x += ex3 * v3.x; acc3.y += ex3 * v3.y; acc3.z += ex3 * v3.z; acc3.w += ex3 * v3.w;
        }
        for (; j < cnt; j++) {
            int s0 = __shfl_sync(0xFFFFFFFFu, idx, j);
            float ex0 = expf(lrelu(g_asrc[s0 * HEADS + hB] + adst_hB));
            float4 v0 = *reinterpret_cast<const float4*>(g_xt + s0 * OUT_DIM + lane * 4);
            exsum += ex0;
            acc0.x += ex0 * v0.x; acc0.y += ex0 * v0.y;
            acc0.z += ex0 * v0.z; acc0.w += ex0 * v0.w;
        }
    }

    // self-loop
    {
        float ex = expf(lrelu(g_asrc[d * HEADS + hB] + adst_hB));
        float4 v = *reinterpret_cast<const float4*>(g_xt + d * OUT_DIM + lane * 4);
        exsum += ex;
        acc0.x += ex * v.x; acc0.y += ex * v.y;
        acc0.z += ex * v.z; acc0.w += ex * v.w;
    }

    float inv_es = 1.f / (exsum + 1e-16f);
    float4 acc;
    acc.x = ((acc0.x + acc1.x) + (acc2.x + acc3.x)) * inv_es;
    acc.y = ((acc0.y + acc1.y) + (acc2.y + acc3.y)) * inv_es;
    acc.z = ((acc0.z + acc1.z) + (acc2.z + acc3.z)) * inv_es;
    acc.w = ((acc0.w + acc1.w) + (acc2.w + acc3.w)) * inv_es;

    // ---- residual GEMV (per-warp smem x row, coalesced transposed weights) ----
    __shared__ float sx[8][IN_CH];
    sx[w][lane]      = x[d * IN_CH + lane];
    sx[w][lane + 32] = x[d * IN_CH + lane + 32];
    __syncwarp();

    float4 r = make_float4(0.f, 0.f, 0.f, 0.f);
#pragma unroll
    for (int k = 0; k < IN_CH; k++) {
        float xv = sx[w][k];
        float4 wv = *reinterpret_cast<const float4*>(g_reswT + k * OUT_DIM + lane * 4);
        r.x += xv * wv.x; r.y += xv * wv.y; r.z += xv * wv.z; r.w += xv * wv.w;
    }

    int t0 = lane * 4;
    float4 gb  = *reinterpret_cast<const float4*>(gat_bias + t0);
    float4 rb  = *reinterpret_cast<const float4*>(res_b + t0);
    float4 z;
    z.x = acc.x + gb.x + r.x + rb.x;
    z.y = acc.y + gb.y + r.y + rb.y;
    z.z = acc.z + gb.z + r.z + rb.z;
    z.w = acc.w + gb.w + r.w + rb.w;

    // ---- LayerNorm over 128 (warp reduce) ----
    float sum = z.x + z.y + z.z + z.w;
#pragma unroll
    for (int o = 16; o; o >>= 1) sum += __shfl_xor_sync(0xFFFFFFFFu, sum, o);
    float mu = sum * (1.f / OUT_DIM);

    float4 zc;
    zc.x = z.x - mu; zc.y = z.y - mu; zc.z = z.z - mu; zc.w = z.w - mu;
    float vv = zc.x * zc.x + zc.y * zc.y + zc.z * zc.z + zc.w * zc.w;
#pragma unroll
    for (int o = 16; o; o >>= 1) vv += __shfl_xor_sync(0xFFFFFFFFu, vv, o);
    float rs = rsqrtf(vv * (1.f / OUT_DIM) + 1e-5f);

    float4 lg = *reinterpret_cast<const float4*>(ln_g + t0);
    float4 lb = *reinterpret_cast<const float4*>(ln_b + t0);
    float4 o4;
    o4.x = lrelu(zc.x * rs * lg.x + lb.x);
    o4.y = lrelu(zc.y * rs * lg.y + lb.y);
    o4.z = lrelu(zc.z * rs * lg.z + lb.z);
    o4.w = lrelu(zc.w * rs * lg.w + lb.w);
    *reinterpret_cast<float4*>(out + d * OUT_DIM + t0) = o4;
}

// ---------------------------------------------------------------------------
extern "C" void kernel_launch(void* const* d_in, const int* in_sizes, int n_in,
                              void* d_out, int out_size)
{
    const float* x        = (const float*)d_in[0];
    const int*   ei       = (const int*)d_in[1];     // int32 (JAX x64 disabled)
    const float* lin_w    = (const float*)d_in[2];
    const float* att_src  = (const float*)d_in[3];
    const float* att_dst  = (const float*)d_in[4];
    const float* gat_bias = (const float*)d_in[5];
    const float* res_w    = (const float*)d_in[6];
    const float* res_b    = (const float*)d_in[7];
    const float* ln_g     = (const float*)d_in[8];
    const float* ln_b     = (const float*)d_in[9];
    float* out = (float*)d_out;

    int N = in_sizes[0] / IN_CH;     // 50000
    int E = in_sizes[1] / 2;         // 800000
    if (N > NN) N = NN;              // clamp to static scratch capacity
    if (E > NE) E = NE;

    int NB = (N + SCAN_TILE - 1) / SCAN_TILE;   // <= 98

    k_fused_prep<<<32 + (E + 255) / 256, 256>>>(lin_w, res_w, ei, E, N);
    k_node_prep<<<(N + 7) / 8, 256>>>(x, att_src, att_dst, N);
    k_scan1<<<NB, SCAN_TILE>>>(N);
    k_scan23<<<NB, SCAN_TILE>>>(N, NB);
    k_fill<<<(E + 255) / 256, 256>>>(ei, E, N);
    k_aggregate<<<(N + 7) / 8, 256>>>(x, res_b, gat_bias, ln_g, ln_b, out, N);
}

// round 16
// speedup vs baseline: 1.3234x; 1.3234x over previous
#include <cuda_runtime.h>
#include <cuda_bf16.h>

// Problem constants (reference shapes are fixed)
#define NN 50000
#define NE 800000
#define IN_CH 64
#define OUT_DIM 128
#define HEADS 4
#define CPH 32           // channels per head
#define NEG 0.2f
#define SCAN_TILE 512

// Scratch (static __device__ — allocations are forbidden)
__device__ float g_xt[NN * OUT_DIM];        // transformed features [N,128] (25.6 MB)
__device__ float g_res[NN * OUT_DIM];       // residual x@res_w^T      [N,128] (25.6 MB)
__device__ float g_asrc[NN * HEADS];        // per-node src attention half
__device__ float g_adst[NN * HEADS];        // per-node dst attention half
__device__ float g_linwT[IN_CH * OUT_DIM];  // lin_w transposed [k][t]
__device__ float g_reswT[IN_CH * OUT_DIM];  // res_w transposed [k][t]
__device__ int   g_deg[NN];                 // in-degree per dst (zeroed by k_scan1 each call)
__device__ int   g_rowptr[NN];              // CSR row start
__device__ int   g_cursor[NN];              // fill cursor (== row end after fill)
__device__ int   g_srcs[NE];                // CSR column (source node ids)
__device__ int   g_bsum[128];               // per-block scan totals

__device__ __forceinline__ float lrelu(float v) { return v >= 0.f ? v : NEG * v; }
__device__ __forceinline__ int clampi(int v, int n) {
    return v < 0 ? 0 : (v >= n ? n - 1 : v);
}

// ---------------------------------------------------------------------------
// Kernel 1 (fused): weight transpose (blocks 0..31) + in-degree count (rest)
// g_deg is guaranteed zero at entry: zero-init at load, re-zeroed by k_scan1.
// ---------------------------------------------------------------------------
__global__ void __launch_bounds__(256) k_fused_prep(
    const float* __restrict__ lin_w, const float* __restrict__ res_w,
    const int* __restrict__ ei, int E, int N)
{
    int b = blockIdx.x;
    int t = threadIdx.x;
    if (b < 32) {
        int idx = b * 256 + t;
        int k  = idx >> 7;        // 0..63
        int tt = idx & 127;       // 0..127
        g_linwT[k * OUT_DIM + tt] = lin_w[tt * IN_CH + k];
        g_reswT[k * OUT_DIM + tt] = res_w[tt * IN_CH + k];
    } else {
        int e = (b - 32) * 256 + t;
        if (e < E) {
            int d = clampi(ei[E + e], N);
            atomicAdd(&g_deg[d], 1);
        }
    }
}

// ---------------------------------------------------------------------------
// Kernel 2: block = 256 thr, 32 nodes/block; each warp register-tiles 4 nodes.
// Computes BOTH xt = x@lin_w^T and res = x@res_w^T with each weight float4
// loaded once per 4 nodes (4x L1 traffic reduction), plus attention halves.
// ---------------------------------------------------------------------------
__global__ void __launch_bounds__(256) k_node_prep(
    const float* __restrict__ x,
    const float* __restrict__ att_src, const float* __restrict__ att_dst, int N)
{
    int t = threadIdx.x;
    int w = t >> 5, lane = t & 31;
    int base = blockIdx.x * 32;

    __shared__ float sx[32 * IN_CH];   // 8 KB
    {
        const float4* xsrc = reinterpret_cast<const float4*>(x) + (size_t)base * (IN_CH / 4);
        float4* sx4 = reinterpret_cast<float4*>(sx);
        int avail = (N - base) * (IN_CH / 4);
        if (avail > 32 * IN_CH / 4) avail = 32 * IN_CH / 4;
        for (int i = t; i < 32 * IN_CH / 4; i += 256)
            sx4[i] = (i < avail) ? xsrc[i] : make_float4(0.f, 0.f, 0.f, 0.f);
    }
    __syncthreads();

    float4 aL0 = make_float4(0,0,0,0), aL1 = aL0, aL2 = aL0, aL3 = aL0;
    float4 aR0 = aL0, aR1 = aL0, aR2 = aL0, aR3 = aL0;
    const float* sxw = sx + (w * 4) * IN_CH;

#pragma unroll
    for (int k = 0; k < IN_CH; k++) {
        float4 wl = *reinterpret_cast<const float4*>(g_linwT + k * OUT_DIM + lane * 4);
        float4 wr = *reinterpret_cast<const float4*>(g_reswT + k * OUT_DIM + lane * 4);
        float x0 = sxw[0 * IN_CH + k];
        float x1 = sxw[1 * IN_CH + k];
        float x2 = sxw[2 * IN_CH + k];
        float x3 = sxw[3 * IN_CH + k];
        aL0.x += x0*wl.x; aL0.y += x0*wl.y; aL0.z += x0*wl.z; aL0.w += x0*wl.w;
        aL1.x += x1*wl.x; aL1.y += x1*wl.y; aL1.z += x1*wl.z; aL1.w += x1*wl.w;
        aL2.x += x2*wl.x; aL2.y += x2*wl.y; aL2.z += x2*wl.z; aL2.w += x2*wl.w;
        aL3.x += x3*wl.x; aL3.y += x3*wl.y; aL3.z += x3*wl.z; aL3.w += x3*wl.w;
        aR0.x += x0*wr.x; aR0.y += x0*wr.y; aR0.z += x0*wr.z; aR0.w += x0*wr.w;
        aR1.x += x1*wr.x; aR1.y += x1*wr.y; aR1.z += x1*wr.z; aR1.w += x1*wr.w;
        aR2.x += x2*wr.x; aR2.y += x2*wr.y; aR2.z += x2*wr.z; aR2.w += x2*wr.w;
        aR3.x += x3*wr.x; aR3.y += x3*wr.y; aR3.z += x3*wr.z; aR3.w += x3*wr.w;
    }

    int hB = lane >> 3;
    int cg = (lane & 7) * 4;
    float4 s4 = *reinterpret_cast<const float4*>(att_src + hB * CPH + cg);
    float4 d4 = *reinterpret_cast<const float4*>(att_dst + hB * CPH + cg);

    float4 accL[4] = {aL0, aL1, aL2, aL3};
    float4 accR[4] = {aR0, aR1, aR2, aR3};
#pragma unroll
    for (int m = 0; m < 4; m++) {
        int n = base + w * 4 + m;
        float4 a = accL[m];
        float as = a.x * s4.x + a.y * s4.y + a.z * s4.z + a.w * s4.w;
        float ad = a.x * d4.x + a.y * d4.y + a.z * d4.z + a.w * d4.w;
#pragma unroll
        for (int o = 1; o < 8; o <<= 1) {
            as += __shfl_xor_sync(0xFFFFFFFFu, as, o);
            ad += __shfl_xor_sync(0xFFFFFFFFu, ad, o);
        }
        if (n < N) {
            *reinterpret_cast<float4*>(g_xt  + n * OUT_DIM + lane * 4) = a;
            *reinterpret_cast<float4*>(g_res + n * OUT_DIM + lane * 4) = accR[m];
            if ((lane & 7) == 0) {
                g_asrc[n * HEADS + hB] = as;
                g_adst[n * HEADS + hB] = ad;
            }
        }
    }
}

// ---------------------------------------------------------------------------
// Kernel 3: per-tile exclusive scan + block totals; zeroes g_deg after read
// ---------------------------------------------------------------------------
__global__ void __launch_bounds__(SCAN_TILE) k_scan1(int N)
{
    int t = threadIdx.x;
    int i = blockIdx.x * SCAN_TILE + t;
    int v = 0;
    if (i < N) {
        v = g_deg[i];
        g_deg[i] = 0;    // reset for next call's count phase
    }

    int lane = t & 31, wid = t >> 5;
    int inc = v;
#pragma unroll
    for (int o = 1; o < 32; o <<= 1) {
        int u = __shfl_up_sync(0xFFFFFFFFu, inc, o);
        if (lane >= o) inc += u;
    }
    __shared__ int ws[16];
    if (lane == 31) ws[wid] = inc;
    __syncthreads();
    if (t < 16) {
        int s = ws[t];
        int inc2 = s;
#pragma unroll
        for (int o = 1; o < 16; o <<= 1) {
            int u = __shfl_up_sync(0xFFFFu, inc2, o);
            if (t >= o) inc2 += u;
        }
        ws[t] = inc2 - s;                    // exclusive warp offset
        if (t == 15) g_bsum[blockIdx.x] = inc2;   // block total
    }
    __syncthreads();
    if (i < N) g_rowptr[i] = inc - v + ws[wid];  // block-local exclusive
}

// ---------------------------------------------------------------------------
// Kernel 4 (fused scan2+scan3): all threads hit every barrier.
// ---------------------------------------------------------------------------
__global__ void __launch_bounds__(SCAN_TILE) k_scan23(int N, int NB)
{
    __shared__ int s[128];
    int t = threadIdx.x;
    if (t < 128) s[t] = (t < NB) ? g_bsum[t] : 0;
    __syncthreads();
    for (int off = 1; off < 128; off <<= 1) {
        int u = (t < 128 && t >= off) ? s[t - off] : 0;
        __syncthreads();
        if (t < 128) s[t] += u;
        __syncthreads();
    }
    int myoff = (blockIdx.x == 0) ? 0 : s[blockIdx.x - 1];   // exclusive offset
    int i = blockIdx.x * SCAN_TILE + t;
    if (i < N) {
        int r = g_rowptr[i] + myoff;
        g_rowptr[i] = r;
        g_cursor[i] = r;
    }
}

// ---------------------------------------------------------------------------
// Kernel 5: fill CSR columns
// ---------------------------------------------------------------------------
__global__ void __launch_bounds__(256) k_fill(const int* __restrict__ ei, int E, int N)
{
    int e = blockIdx.x * blockDim.x + threadIdx.x;
    if (e >= E) return;
    int s = clampi(ei[e], N);
    int d = clampi(ei[E + e], N);
    int p = atomicAdd(&g_cursor[d], 1);
    g_srcs[p] = s;
}

// ---------------------------------------------------------------------------
// Kernel 6: one warp per dst node — single-pass weighted aggregation,
// unrolled x4; residual row read from g_res (precomputed); LN; LeakyReLU.
// block = 256 (8 warps = 8 nodes), grid = ceil(N/8)
// ---------------------------------------------------------------------------
__global__ void __launch_bounds__(256) k_aggregate(
    const float* __restrict__ res_b, const float* __restrict__ gat_bias,
    const float* __restrict__ ln_g, const float* __restrict__ ln_b,
    float* __restrict__ out, int N)
{
    int w    = threadIdx.x >> 5;
    int lane = threadIdx.x & 31;
    int d = blockIdx.x * 8 + w;
    if (d >= N) return;

    int r0 = g_rowptr[d];
    int r1 = g_cursor[d];          // == row end after fill

    int hB = lane >> 3;            // head for this lane's 4 channels
    float adst_hB = g_adst[d * HEADS + hB];

    float4 acc0 = make_float4(0.f, 0.f, 0.f, 0.f);
    float4 acc1 = make_float4(0.f, 0.f, 0.f, 0.f);
    float4 acc2 = make_float4(0.f, 0.f, 0.f, 0.f);
    float4 acc3 = make_float4(0.f, 0.f, 0.f, 0.f);
    float exsum = 0.f;

    for (int base = r0; base < r1; base += 32) {
        int cnt = r1 - base; if (cnt > 32) cnt = 32;
        int idx = (base + lane < r1) ? g_srcs[base + lane] : 0;

        int j = 0;
        for (; j + 3 < cnt; j += 4) {
            int s0 = __shfl_sync(0xFFFFFFFFu, idx, j);
            int s1 = __shfl_sync(0xFFFFFFFFu, idx, j + 1);
            int s2 = __shfl_sync(0xFFFFFFFFu, idx, j + 2);
            int s3 = __shfl_sync(0xFFFFFFFFu, idx, j + 3);
            float a0 = g_asrc[s0 * HEADS + hB];
            float a1 = g_asrc[s1 * HEADS + hB];
            float a2 = g_asrc[s2 * HEADS + hB];
            float a3 = g_asrc[s3 * HEADS + hB];
            float4 v0 = *reinterpret_cast<const float4*>(g_xt + s0 * OUT_DIM + lane * 4);
            float4 v1 = *reinterpret_cast<const float4*>(g_xt + s1 * OUT_DIM + lane * 4);
            float4 v2 = *reinterpret_cast<const float4*>(g_xt + s2 * OUT_DIM + lane * 4);
            float4 v3 = *reinterpret_cast<const float4*>(g_xt + s3 * OUT_DIM + lane * 4);
            float ex0 = expf(lrelu(a0 + adst_hB));
            float ex1 = expf(lrelu(a1 + adst_hB));
            float ex2 = expf(lrelu(a2 + adst_hB));
            float ex3 = expf(lrelu(a3 + adst_hB));
            exsum += (ex0 + ex1) + (ex2 + ex3);
            acc0.x += ex0 * v0.x; acc0.y += ex0 * v0.y; acc0.z += ex0 * v0.z; acc0.w += ex0 * v0.w;
            acc1.x += ex1 * v1.x; acc1.y += ex1 * v1.y; acc1.z += ex1 * v1.z; acc1.w += ex1 * v1.w;
            acc2.x += ex2 * v2.x; acc2.y += ex2 * v2.y; acc2.z += ex2 * v2.z; acc2.w += ex2 * v2.w;
            acc3.x += ex3 * v3.x; acc3.y += ex3 * v3.y; acc3.z += ex3 * v3.z; acc3.w += ex3 * v3.w;
        }
        for (; j < cnt; j++) {
            int s0 = __shfl_sync(0xFFFFFFFFu, idx, j);
            float ex0 = expf(lrelu(g_asrc[s0 * HEADS + hB] + adst_hB));
            float4 v0 = *reinterpret_cast<const float4*>(g_xt + s0 * OUT_DIM + lane * 4);
            exsum += ex0;
            acc0.x += ex0 * v0.x; acc0.y += ex0 * v0.y;
            acc0.z += ex0 * v0.z; acc0.w += ex0 * v0.w;
        }
    }

    // self-loop
    {
        float ex = expf(lrelu(g_asrc[d * HEADS + hB] + adst_hB));
        float4 v = *reinterpret_cast<const float4*>(g_xt + d * OUT_DIM + lane * 4);
        exsum += ex;
        acc0.x += ex * v.x; acc0.y += ex * v.y;
        acc0.z += ex * v.z; acc0.w += ex * v.w;
    }

    float inv_es = 1.f / (exsum + 1e-16f);
    float4 acc;
    acc.x = ((acc0.x + acc1.x) + (acc2.x + acc3.x)) * inv_es;
    acc.y = ((acc0.y + acc1.y) + (acc2.y + acc3.y)) * inv_es;
    acc.z = ((acc0.z + acc1.z) + (acc2.z + acc3.z)) * inv_es;
    acc.w = ((acc0.w + acc1.w) + (acc2.w + acc3.w)) * inv_es;

    // ---- residual from precomputed g_res (coalesced stream read) ----
    int t0 = lane * 4;
    float4 r   = *reinterpret_cast<const float4*>(g_res + d * OUT_DIM + t0);
    float4 gb  = *reinterpret_cast<const float4*>(gat_bias + t0);
    float4 rb  = *reinterpret_cast<const float4*>(res_b + t0);
    float4 z;
    z.x = acc.x + gb.x + r.x + rb.x;
    z.y = acc.y + gb.y + r.y + rb.y;
    z.z = acc.z + gb.z + r.z + rb.z;
    z.w = acc.w + gb.w + r.w + rb.w;

    // ---- LayerNorm over 128 (warp reduce) ----
    float sum = z.x + z.y + z.z + z.w;
#pragma unroll
    for (int o = 16; o; o >>= 1) sum += __shfl_xor_sync(0xFFFFFFFFu, sum, o);
    float mu = sum * (1.f / OUT_DIM);

    float4 zc;
    zc.x = z.x - mu; zc.y = z.y - mu; zc.z = z.z - mu; zc.w = z.w - mu;
    float vv = zc.x * zc.x + zc.y * zc.y + zc.z * zc.z + zc.w * zc.w;
#pragma unroll
    for (int o = 16; o; o >>= 1) vv += __shfl_xor_sync(0xFFFFFFFFu, vv, o);
    float rs = rsqrtf(vv * (1.f / OUT_DIM) + 1e-5f);

    float4 lg = *reinterpret_cast<const float4*>(ln_g + t0);
    float4 lb = *reinterpret_cast<const float4*>(ln_b + t0);
    float4 o4;
    o4.x = lrelu(zc.x * rs * lg.x + lb.x);
    o4.y = lrelu(zc.y * rs * lg.y + lb.y);
    o4.z = lrelu(zc.z * rs * lg.z + lb.z);
    o4.w = lrelu(zc.w * rs * lg.w + lb.w);
    *reinterpret_cast<float4*>(out + d * OUT_DIM + t0) = o4;
}

// ---------------------------------------------------------------------------
extern "C" void kernel_launch(void* const* d_in, const int* in_sizes, int n_in,
                              void* d_out, int out_size)
{
    const float* x        = (const float*)d_in[0];
    const int*   ei       = (const int*)d_in[1];     // int32 (JAX x64 disabled)
    const float* lin_w    = (const float*)d_in[2];
    const float* att_src  = (const float*)d_in[3];
    const float* att_dst  = (const float*)d_in[4];
    const float* gat_bias = (const float*)d_in[5];
    const float* res_w    = (const float*)d_in[6];
    const float* res_b    = (const float*)d_in[7];
    const float* ln_g     = (const float*)d_in[8];
    const float* ln_b     = (const float*)d_in[9];
    float* out = (float*)d_out;

    int N = in_sizes[0] / IN_CH;     // 50000
    int E = in_sizes[1] / 2;         // 800000
    if (N > NN) N = NN;              // clamp to static scratch capacity
    if (E > NE) E = NE;

    int NB = (N + SCAN_TILE - 1) / SCAN_TILE;   // <= 98

    k_fused_prep<<<32 + (E + 255) / 256, 256>>>(lin_w, res_w, ei, E, N);
    k_node_prep<<<(N + 31) / 32, 256>>>(x, att_src, att_dst, N);
    k_scan1<<<NB, SCAN_TILE>>>(N);
    k_scan23<<<NB, SCAN_TILE>>>(N, NB);
    k_fill<<<(E + 255) / 256, 256>>>(ei, E, N);
    k_aggregate<<<(N + 7) / 8, 256>>>(res_b, gat_bias, ln_g, ln_b, out, N);
}

// round 17
// speedup vs baseline: 1.4408x; 1.0887x over previous
#include <cuda_runtime.h>
#include <cuda_fp16.h>

// Problem constants (reference shapes are fixed)
#define NN 50000
#define NE 800000
#define IN_CH 64
#define OUT_DIM 128
#define HEADS 4
#define CPH 32           // channels per head
#define NEG 0.2f
#define SCAN_TILE 512

// Scratch (static __device__ — allocations are forbidden)
__device__ __half g_xth[NN * OUT_DIM];      // transformed features, fp16 (12.8 MB)
__device__ float  g_res[NN * OUT_DIM];      // residual x@res_w^T (25.6 MB)
__device__ float  g_asrc[NN * HEADS];       // per-node src attention half (fp32)
__device__ float  g_adst[NN * HEADS];       // per-node dst attention half (fp32)
__device__ float  g_linwT[IN_CH * OUT_DIM]; // lin_w transposed [k][t]
__device__ float  g_reswT[IN_CH * OUT_DIM]; // res_w transposed [k][t]
__device__ int    g_deg[NN];                // in-degree per dst (zeroed by k_scan1)
__device__ int    g_rowptr[NN];             // CSR row start
__device__ int    g_cursor[NN];             // fill cursor (== row end after fill)
__device__ int    g_srcs[NE];               // CSR column (source node ids)
__device__ int    g_bsum[128];              // per-block scan totals

__device__ __forceinline__ float lrelu(float v) { return v >= 0.f ? v : NEG * v; }
__device__ __forceinline__ int clampi(int v, int n) {
    return v < 0 ? 0 : (v >= n ? n - 1 : v);
}

// unpack 4 halves (as uint2) to float4, FMA into acc with weight ex
__device__ __forceinline__ void fma_h4(float4& acc, uint2 u, float ex) {
    __half2 h01 = *reinterpret_cast<__half2*>(&u.x);
    __half2 h23 = *reinterpret_cast<__half2*>(&u.y);
    float2 f01 = __half22float2(h01);
    float2 f23 = __half22float2(h23);
    acc.x += ex * f01.x; acc.y += ex * f01.y;
    acc.z += ex * f23.x; acc.w += ex * f23.y;
}

// ---------------------------------------------------------------------------
// Kernel 1 (fused): weight transpose (blocks 0..31) + in-degree count (rest)
// ---------------------------------------------------------------------------
__global__ void __launch_bounds__(256) k_fused_prep(
    const float* __restrict__ lin_w, const float* __restrict__ res_w,
    const int* __restrict__ ei, int E, int N)
{
    int b = blockIdx.x;
    int t = threadIdx.x;
    if (b < 32) {
        int idx = b * 256 + t;
        int k  = idx >> 7;        // 0..63
        int tt = idx & 127;       // 0..127
        g_linwT[k * OUT_DIM + tt] = lin_w[tt * IN_CH + k];
        g_reswT[k * OUT_DIM + tt] = res_w[tt * IN_CH + k];
    } else {
        int e = (b - 32) * 256 + t;
        if (e < E) {
            int d = clampi(ei[E + e], N);
            atomicAdd(&g_deg[d], 1);
        }
    }
}

// ---------------------------------------------------------------------------
// Kernel 2: 32 nodes/block; each warp register-tiles 4 nodes; computes
// xt (stored fp16) and res (fp32) with 4x weight reuse; attention halves fp32.
// ---------------------------------------------------------------------------
__global__ void __launch_bounds__(256) k_node_prep(
    const float* __restrict__ x,
    const float* __restrict__ att_src, const float* __restrict__ att_dst, int N)
{
    int t = threadIdx.x;
    int w = t >> 5, lane = t & 31;
    int base = blockIdx.x * 32;

    __shared__ float sx[32 * IN_CH];   // 8 KB
    {
        const float4* xsrc = reinterpret_cast<const float4*>(x) + (size_t)base * (IN_CH / 4);
        float4* sx4 = reinterpret_cast<float4*>(sx);
        int avail = (N - base) * (IN_CH / 4);
        if (avail > 32 * IN_CH / 4) avail = 32 * IN_CH / 4;
        for (int i = t; i < 32 * IN_CH / 4; i += 256)
            sx4[i] = (i < avail) ? xsrc[i] : make_float4(0.f, 0.f, 0.f, 0.f);
    }
    __syncthreads();

    float4 aL0 = make_float4(0,0,0,0), aL1 = aL0, aL2 = aL0, aL3 = aL0;
    float4 aR0 = aL0, aR1 = aL0, aR2 = aL0, aR3 = aL0;
    const float* sxw = sx + (w * 4) * IN_CH;

#pragma unroll
    for (int k = 0; k < IN_CH; k++) {
        float4 wl = *reinterpret_cast<const float4*>(g_linwT + k * OUT_DIM + lane * 4);
        float4 wr = *reinterpret_cast<const float4*>(g_reswT + k * OUT_DIM + lane * 4);
        float x0 = sxw[0 * IN_CH + k];
        float x1 = sxw[1 * IN_CH + k];
        float x2 = sxw[2 * IN_CH + k];
        float x3 = sxw[3 * IN_CH + k];
        aL0.x += x0*wl.x; aL0.y += x0*wl.y; aL0.z += x0*wl.z; aL0.w += x0*wl.w;
        aL1.x += x1*wl.x; aL1.y += x1*wl.y; aL1.z += x1*wl.z; aL1.w += x1*wl.w;
        aL2.x += x2*wl.x; aL2.y += x2*wl.y; aL2.z += x2*wl.z; aL2.w += x2*wl.w;
        aL3.x += x3*wl.x; aL3.y += x3*wl.y; aL3.z += x3*wl.z; aL3.w += x3*wl.w;
        aR0.x += x0*wr.x; aR0.y += x0*wr.y; aR0.z += x0*wr.z; aR0.w += x0*wr.w;
        aR1.x += x1*wr.x; aR1.y += x1*wr.y; aR1.z += x1*wr.z; aR1.w += x1*wr.w;
        aR2.x += x2*wr.x; aR2.y += x2*wr.y; aR2.z += x2*wr.z; aR2.w += x2*wr.w;
        aR3.x += x3*wr.x; aR3.y += x3*wr.y; aR3.z += x3*wr.z; aR3.w += x3*wr.w;
    }

    int hB = lane >> 3;
    int cg = (lane & 7) * 4;
    float4 s4 = *reinterpret_cast<const float4*>(att_src + hB * CPH + cg);
    float4 d4 = *reinterpret_cast<const float4*>(att_dst + hB * CPH + cg);

    float4 accL[4] = {aL0, aL1, aL2, aL3};
    float4 accR[4] = {aR0, aR1, aR2, aR3};
#pragma unroll
    for (int m = 0; m < 4; m++) {
        int n = base + w * 4 + m;
        float4 a = accL[m];
        float as = a.x * s4.x + a.y * s4.y + a.z * s4.z + a.w * s4.w;
        float ad = a.x * d4.x + a.y * d4.y + a.z * d4.z + a.w * d4.w;
#pragma unroll
        for (int o = 1; o < 8; o <<= 1) {
            as += __shfl_xor_sync(0xFFFFFFFFu, as, o);
            ad += __shfl_xor_sync(0xFFFFFFFFu, ad, o);
        }
        if (n < N) {
            // store xt as fp16 (half4 packed in uint2)
            __half2 p0 = __floats2half2_rn(a.x, a.y);
            __half2 p1 = __floats2half2_rn(a.z, a.w);
            uint2 u;
            u.x = *reinterpret_cast<unsigned*>(&p0);
            u.y = *reinterpret_cast<unsigned*>(&p1);
            *reinterpret_cast<uint2*>(g_xth + n * OUT_DIM + lane * 4) = u;
            *reinterpret_cast<float4*>(g_res + n * OUT_DIM + lane * 4) = accR[m];
            if ((lane & 7) == 0) {
                g_asrc[n * HEADS + hB] = as;
                g_adst[n * HEADS + hB] = ad;
            }
        }
    }
}

// ---------------------------------------------------------------------------
// Kernel 3: per-tile exclusive scan + block totals; zeroes g_deg after read
// ---------------------------------------------------------------------------
__global__ void __launch_bounds__(SCAN_TILE) k_scan1(int N)
{
    int t = threadIdx.x;
    int i = blockIdx.x * SCAN_TILE + t;
    int v = 0;
    if (i < N) {
        v = g_deg[i];
        g_deg[i] = 0;    // reset for next call's count phase
    }

    int lane = t & 31, wid = t >> 5;
    int inc = v;
#pragma unroll
    for (int o = 1; o < 32; o <<= 1) {
        int u = __shfl_up_sync(0xFFFFFFFFu, inc, o);
        if (lane >= o) inc += u;
    }
    __shared__ int ws[16];
    if (lane == 31) ws[wid] = inc;
    __syncthreads();
    if (t < 16) {
        int s = ws[t];
        int inc2 = s;
#pragma unroll
        for (int o = 1; o < 16; o <<= 1) {
            int u = __shfl_up_sync(0xFFFFu, inc2, o);
            if (t >= o) inc2 += u;
        }
        ws[t] = inc2 - s;                    // exclusive warp offset
        if (t == 15) g_bsum[blockIdx.x] = inc2;   // block total
    }
    __syncthreads();
    if (i < N) g_rowptr[i] = inc - v + ws[wid];  // block-local exclusive
}

// ---------------------------------------------------------------------------
// Kernel 4 (fused scan2+scan3): all threads hit every barrier.
// ---------------------------------------------------------------------------
__global__ void __launch_bounds__(SCAN_TILE) k_scan23(int N, int NB)
{
    __shared__ int s[128];
    int t = threadIdx.x;
    if (t < 128) s[t] = (t < NB) ? g_bsum[t] : 0;
    __syncthreads();
    for (int off = 1; off < 128; off <<= 1) {
        int u = (t < 128 && t >= off) ? s[t - off] : 0;
        __syncthreads();
        if (t < 128) s[t] += u;
        __syncthreads();
    }
    int myoff = (blockIdx.x == 0) ? 0 : s[blockIdx.x - 1];   // exclusive offset
    int i = blockIdx.x * SCAN_TILE + t;
    if (i < N) {
        int r = g_rowptr[i] + myoff;
        g_rowptr[i] = r;
        g_cursor[i] = r;
    }
}

// ---------------------------------------------------------------------------
// Kernel 5: fill CSR columns
// ---------------------------------------------------------------------------
__global__ void __launch_bounds__(256) k_fill(const int* __restrict__ ei, int E, int N)
{
    int e = blockIdx.x * blockDim.x + threadIdx.x;
    if (e >= E) return;
    int s = clampi(ei[e], N);
    int d = clampi(ei[E + e], N);
    int p = atomicAdd(&g_cursor[d], 1);
    g_srcs[p] = s;
}

// ---------------------------------------------------------------------------
// Kernel 6: one warp per dst node — single-pass weighted aggregation over
// fp16 xt rows (8B/lane), fp32 accumulation; residual from g_res; LN; lrelu.
// block = 256 (8 warps = 8 nodes), grid = ceil(N/8)
// ---------------------------------------------------------------------------
__global__ void __launch_bounds__(256) k_aggregate(
    const float* __restrict__ res_b, const float* __restrict__ gat_bias,
    const float* __restrict__ ln_g, const float* __restrict__ ln_b,
    float* __restrict__ out, int N)
{
    int w    = threadIdx.x >> 5;
    int lane = threadIdx.x & 31;
    int d = blockIdx.x * 8 + w;
    if (d >= N) return;

    int r0 = g_rowptr[d];
    int r1 = g_cursor[d];          // == row end after fill

    int hB = lane >> 3;            // head for this lane's 4 channels
    float adst_hB = g_adst[d * HEADS + hB];

    float4 acc0 = make_float4(0.f, 0.f, 0.f, 0.f);
    float4 acc1 = make_float4(0.f, 0.f, 0.f, 0.f);
    float4 acc2 = make_float4(0.f, 0.f, 0.f, 0.f);
    float4 acc3 = make_float4(0.f, 0.f, 0.f, 0.f);
    float exsum = 0.f;

    for (int base = r0; base < r1; base += 32) {
        int cnt = r1 - base; if (cnt > 32) cnt = 32;
        int idx = (base + lane < r1) ? g_srcs[base + lane] : 0;

        int j = 0;
        for (; j + 3 < cnt; j += 4) {
            int s0 = __shfl_sync(0xFFFFFFFFu, idx, j);
            int s1 = __shfl_sync(0xFFFFFFFFu, idx, j + 1);
            int s2 = __shfl_sync(0xFFFFFFFFu, idx, j + 2);
            int s3 = __shfl_sync(0xFFFFFFFFu, idx, j + 3);
            float a0 = g_asrc[s0 * HEADS + hB];
            float a1 = g_asrc[s1 * HEADS + hB];
            float a2 = g_asrc[s2 * HEADS + hB];
            float a3 = g_asrc[s3 * HEADS + hB];
            uint2 u0 = *reinterpret_cast<const uint2*>(g_xth + s0 * OUT_DIM + lane * 4);
            uint2 u1 = *reinterpret_cast<const uint2*>(g_xth + s1 * OUT_DIM + lane * 4);
            uint2 u2 = *reinterpret_cast<const uint2*>(g_xth + s2 * OUT_DIM + lane * 4);
            uint2 u3 = *reinterpret_cast<const uint2*>(g_xth + s3 * OUT_DIM + lane * 4);
            float ex0 = expf(lrelu(a0 + adst_hB));
            float ex1 = expf(lrelu(a1 + adst_hB));
            float ex2 = expf(lrelu(a2 + adst_hB));
            float ex3 = expf(lrelu(a3 + adst_hB));
            exsum += (ex0 + ex1) + (ex2 + ex3);
            fma_h4(acc0, u0, ex0);
            fma_h4(acc1, u1, ex1);
            fma_h4(acc2, u2, ex2);
            fma_h4(acc3, u3, ex3);
        }
        for (; j < cnt; j++) {
            int s0 = __shfl_sync(0xFFFFFFFFu, idx, j);
            float ex0 = expf(lrelu(g_asrc[s0 * HEADS + hB] + adst_hB));
            uint2 u0 = *reinterpret_cast<const uint2*>(g_xth + s0 * OUT_DIM + lane * 4);
            exsum += ex0;
            fma_h4(acc0, u0, ex0);
        }
    }

    // self-loop
    {
        float ex = expf(lrelu(g_asrc[d * HEADS + hB] + adst_hB));
        uint2 u = *reinterpret_cast<const uint2*>(g_xth + d * OUT_DIM + lane * 4);
        exsum += ex;
        fma_h4(acc0, u, ex);
    }

    float inv_es = 1.f / (exsum + 1e-16f);
    float4 acc;
    acc.x = ((acc0.x + acc1.x) + (acc2.x + acc3.x)) * inv_es;
    acc.y = ((acc0.y + acc1.y) + (acc2.y + acc3.y)) * inv_es;
    acc.z = ((acc0.z + acc1.z) + (acc2.z + acc3.z)) * inv_es;
    acc.w = ((acc0.w + acc1.w) + (acc2.w + acc3.w)) * inv_es;

    // ---- residual from precomputed g_res (coalesced stream read) ----
    int t0 = lane * 4;
    float4 r   = *reinterpret_cast<const float4*>(g_res + d * OUT_DIM + t0);
    float4 gb  = *reinterpret_cast<const float4*>(gat_bias + t0);
    float4 rb  = *reinterpret_cast<const float4*>(res_b + t0);
    float4 z;
    z.x = acc.x + gb.x + r.x + rb.x;
    z.y = acc.y + gb.y + r.y + rb.y;
    z.z = acc.z + gb.z + r.z + rb.z;
    z.w = acc.w + gb.w + r.w + rb.w;

    // ---- LayerNorm over 128 (warp reduce) ----
    float sum = z.x + z.y + z.z + z.w;
#pragma unroll
    for (int o = 16; o; o >>= 1) sum += __shfl_xor_sync(0xFFFFFFFFu, sum, o);
    float mu = sum * (1.f / OUT_DIM);

    float4 zc;
    zc.x = z.x - mu; zc.y = z.y - mu; zc.z = z.z - mu; zc.w = z.w - mu;
    float vv = zc.x * zc.x + zc.y * zc.y + zc.z * zc.z + zc.w * zc.w;
#pragma unroll
    for (int o = 16; o; o >>= 1) vv += __shfl_xor_sync(0xFFFFFFFFu, vv, o);
    float rs = rsqrtf(vv * (1.f / OUT_DIM) + 1e-5f);

    float4 lg = *reinterpret_cast<const float4*>(ln_g + t0);
    float4 lb = *reinterpret_cast<const float4*>(ln_b + t0);
    float4 o4;
    o4.x = lrelu(zc.x * rs * lg.x + lb.x);
    o4.y = lrelu(zc.y * rs * lg.y + lb.y);
    o4.z = lrelu(zc.z * rs * lg.z + lb.z);
    o4.w = lrelu(zc.w * rs * lg.w + lb.w);
    *reinterpret_cast<float4*>(out + d * OUT_DIM + t0) = o4;
}

// ---------------------------------------------------------------------------
extern "C" void kernel_launch(void* const* d_in, const int* in_sizes, int n_in,
                              void* d_out, int out_size)
{
    const float* x        = (const float*)d_in[0];
    const int*   ei       = (const int*)d_in[1];     // int32 (JAX x64 disabled)
    const float* lin_w    = (const float*)d_in[2];
    const float* att_src  = (const float*)d_in[3];
    const float* att_dst  = (const float*)d_in[4];
    const float* gat_bias = (const float*)d_in[5];
    const float* res_w    = (const float*)d_in[6];
    const float* res_b    = (const float*)d_in[7];
    const float* ln_g     = (const float*)d_in[8];
    const float* ln_b     = (const float*)d_in[9];
    float* out = (float*)d_out;

    int N = in_sizes[0] / IN_CH;     // 50000
    int E = in_sizes[1] / 2;         // 800000
    if (N > NN) N = NN;              // clamp to static scratch capacity
    if (E > NE) E = NE;

    int NB = (N + SCAN_TILE - 1) / SCAN_TILE;   // <= 98

    k_fused_prep<<<32 + (E + 255) / 256, 256>>>(lin_w, res_w, ei, E, N);
    k_node_prep<<<(N + 31) / 32, 256>>>(x, att_src, att_dst, N);
    k_scan1<<<NB, SCAN_TILE>>>(N);
    k_scan23<<<NB, SCAN_TILE>>>(N, NB);
    k_fill<<<(E + 255) / 256, 256>>>(ei, E, N);
    k_aggregate<<<(N + 7) / 8, 256>>>(res_b, gat_bias, ln_g, ln_b, out, N);
}